// round 5
// baseline (speedup 1.0000x reference)
#include <cuda_runtime.h>
#include <cuda_bf16.h>
#include <math.h>
#include <cstdint>

#define B_    4
#define S_    1024
#define D_    4096
#define H_    32
#define HKV_  8
#define HD_   128
#define KVD_  (HKV_*HD_)   // 1024
#define M_    (B_*S_)      // 4096

// ---------------- scratch (static device globals) ----------------
__device__ __nv_bfloat16 g_xh[M_*D_],  g_xl[M_*D_];     // x split
__device__ __nv_bfloat16 g_qh[M_*D_],  g_ql[M_*D_];     // rope(Q)
__device__ __nv_bfloat16 g_kh[M_*KVD_], g_kl[M_*KVD_];  // rope(K)
__device__ __nv_bfloat16 g_vth[M_*KVD_], g_vtl[M_*KVD_];// V^T [b][hk][d][s]
__device__ __nv_bfloat16 g_oh[M_*D_],  g_ol[M_*D_];     // attn out split
__device__ __nv_bfloat16 g_wqh[D_*D_],   g_wql[D_*D_];
__device__ __nv_bfloat16 g_wkh[D_*KVD_], g_wkl[D_*KVD_];
__device__ __nv_bfloat16 g_wvh[D_*KVD_], g_wvl[D_*KVD_];
__device__ __nv_bfloat16 g_woh[D_*D_],   g_wol[D_*D_];

// ---------------- PTX helpers ----------------
__device__ __forceinline__ uint32_t smem_u32(const void* p) {
    uint32_t a;
    asm("{ .reg .u64 t; cvta.to.shared.u64 t, %1; cvt.u32.u64 %0, t; }" : "=r"(a) : "l"(p));
    return a;
}
#define SW128(off) ((off) ^ (((off) >> 3) & 0x70))
#define CP16(dst, src) asm volatile("cp.async.cg.shared.global [%0], [%1], 16;" :: "r"(dst), "l"(src))
#define CP_COMMIT()    asm volatile("cp.async.commit_group;" ::: "memory")
#define LDSM4(r0, r1, r2, r3, a)                                             \
    asm volatile("ldmatrix.sync.aligned.m8n8.x4.shared.b16 {%0,%1,%2,%3}, [%4];" \
        : "=r"(r0), "=r"(r1), "=r"(r2), "=r"(r3) : "r"(a))
#define MMA_BF16(ac, ar, br)                                                 \
    asm volatile("mma.sync.aligned.m16n8k16.row.col.f32.bf16.bf16.f32 "      \
        "{%0,%1,%2,%3}, {%4,%5,%6,%7}, {%8,%9}, {%0,%1,%2,%3};"              \
        : "+f"((ac)[0]), "+f"((ac)[1]), "+f"((ac)[2]), "+f"((ac)[3])         \
        : "r"((ar)[0]), "r"((ar)[1]), "r"((ar)[2]), "r"((ar)[3]),            \
          "r"((br)[0]), "r"((br)[1]))

__device__ __forceinline__ __nv_bfloat162 split_pair(float a, float b,
                                                     __nv_bfloat162* lo) {
    __nv_bfloat162 h = __floats2bfloat162_rn(a, b);
    *lo = __floats2bfloat162_rn(a - __bfloat162float(h.x), b - __bfloat162float(h.y));
    return h;
}

// ---------------------------------------------------------------------------
// Warp-MMA GEMM: C = (Ah+Al) @ (Bh+Bl)^T, B stored [N,K]; K=4096 always.
// EPI 0: plain fp32 C.  EPI 1: RoPE + bf16 hi/lo split (Q/K proj).
// EPI 2: transpose + split -> [b][hk][d][s] (V proj; tile cols = one head).
// ---------------------------------------------------------------------------
#define EPI_PLAIN 0
#define EPI_ROPE  1
#define EPI_VT    2
#define STAGE_BYTES 65536
#define GEMM_SMEM  (3*STAGE_BYTES + 128)

template<int EPI>
__global__ void __launch_bounds__(256, 1) gemm_tc(const __nv_bfloat16* __restrict__ Ah,
                                                  const __nv_bfloat16* __restrict__ Al,
                                                  const __nv_bfloat16* __restrict__ Bh,
                                                  const __nv_bfloat16* __restrict__ Bl,
                                                  float* __restrict__ C,
                                                  __nv_bfloat16* __restrict__ OH,
                                                  __nv_bfloat16* __restrict__ OL,
                                                  const float* __restrict__ fc,
                                                  const float* __restrict__ fs,
                                                  int N, int K)
{
    extern __shared__ char smem[];
    const uint32_t sb   = smem_u32(smem);
    const uint32_t base = (sb + 127u) & ~127u;
    const int tid  = threadIdx.x;
    const int lane = tid & 31;
    const int wid  = tid >> 5;
    const int wm   = wid & 1;
    const int wn   = wid >> 1;
    const int rowBase = blockIdx.y * 128;
    const int colBase = blockIdx.x * 128;

    float acc[4][4][4];
    #pragma unroll
    for (int mi = 0; mi < 4; mi++)
        #pragma unroll
        for (int ni = 0; ni < 4; ni++)
            #pragma unroll
            for (int r = 0; r < 4; r++) acc[mi][ni][r] = 0.f;

    const int nc = K >> 6;

    #define LOAD_CHUNK(c) do {                                                     \
        const int _s = (c) % 3;                                                    \
        const uint32_t _st = base + _s*STAGE_BYTES;                                \
        const int _kb = (c) * 64;                                                  \
        _Pragma("unroll")                                                          \
        for (int _i = 0; _i < 4; _i++) {                                           \
            const int _id  = tid + _i*256;                                         \
            const int _row = _id >> 3;                                             \
            const int _u   = _id & 7;                                              \
            const uint32_t _sw = SW128((uint32_t)(_row*128 + _u*16));              \
            const size_t _ao = (size_t)(rowBase + _row)*K + _kb + _u*8;            \
            const size_t _bo = (size_t)(colBase + _row)*K + _kb + _u*8;            \
            CP16(_st +         _sw, Ah + _ao);                                     \
            CP16(_st + 16384 + _sw, Al + _ao);                                     \
            CP16(_st + 32768 + _sw, Bh + _bo);                                     \
            CP16(_st + 49152 + _sw, Bl + _bo);                                     \
        }                                                                          \
        CP_COMMIT();                                                               \
    } while (0)

    LOAD_CHUNK(0); LOAD_CHUNK(1);

    for (int c = 0; c < nc; c++) {
        if (c == nc - 1) asm volatile("cp.async.wait_group 0;" ::: "memory");
        else             asm volatile("cp.async.wait_group 1;" ::: "memory");
        __syncthreads();
        if (c + 2 < nc) LOAD_CHUNK(c + 2);

        const uint32_t stA  = base + (c % 3)*STAGE_BYTES;
        const uint32_t stAl = stA + 16384;
        const uint32_t stB  = stA + 32768;
        const uint32_t stBl = stA + 49152;

        #pragma unroll
        for (int ks = 0; ks < 4; ks++) {
            const uint32_t kb = (uint32_t)(ks*32 + (lane >> 4)*16);

            uint32_t ah[4][4], al4[4][4];
            #pragma unroll
            for (int mi = 0; mi < 4; mi++) {
                const uint32_t off = (uint32_t)((wm*64 + mi*16 + (lane & 15)) * 128) + kb;
                const uint32_t sw  = SW128(off);
                LDSM4(ah[mi][0],  ah[mi][1],  ah[mi][2],  ah[mi][3],  stA  + sw);
                LDSM4(al4[mi][0], al4[mi][1], al4[mi][2], al4[mi][3], stAl + sw);
            }
            uint32_t bh[4][2], bl4[4][2];
            #pragma unroll
            for (int nj = 0; nj < 2; nj++) {
                const uint32_t off = (uint32_t)((wn*32 + nj*16 + (lane & 15)) * 128) + kb;
                const uint32_t sw  = SW128(off);
                LDSM4(bh[2*nj][0],  bh[2*nj+1][0],  bh[2*nj][1],  bh[2*nj+1][1],  stB  + sw);
                LDSM4(bl4[2*nj][0], bl4[2*nj+1][0], bl4[2*nj][1], bl4[2*nj+1][1], stBl + sw);
            }

            #pragma unroll
            for (int mi = 0; mi < 4; mi++)
                #pragma unroll
                for (int ni = 0; ni < 4; ni++) {
                    MMA_BF16(acc[mi][ni], ah[mi],  bh[ni]);
                    MMA_BF16(acc[mi][ni], ah[mi],  bl4[ni]);
                    MMA_BF16(acc[mi][ni], al4[mi], bh[ni]);
                }
        }
    }
    #undef LOAD_CHUNK

    if (EPI == EPI_PLAIN) {
        #pragma unroll
        for (int mi = 0; mi < 4; mi++) {
            const int r0 = rowBase + wm*64 + mi*16 + (lane >> 2);
            #pragma unroll
            for (int ni = 0; ni < 4; ni++) {
                const int c0 = colBase + wn*32 + ni*8 + (lane & 3)*2;
                *(float2*)(C + (size_t)r0*N + c0)       = make_float2(acc[mi][ni][0], acc[mi][ni][1]);
                *(float2*)(C + (size_t)(r0 + 8)*N + c0) = make_float2(acc[mi][ni][2], acc[mi][ni][3]);
            }
        }
    } else if (EPI == EPI_ROPE) {
        #pragma unroll
        for (int mi = 0; mi < 4; mi++) {
            const int r0 = rowBase + wm*64 + mi*16 + (lane >> 2);
            const int sA = r0 & (S_ - 1);
            const int sB = (r0 + 8) & (S_ - 1);
            #pragma unroll
            for (int ni = 0; ni < 4; ni++) {
                const int c0 = colBase + wn*32 + ni*8 + (lane & 3)*2;
                const int i  = (c0 & 127) >> 1;
                const float cA = __ldg(fc + sA*64 + i), snA = __ldg(fs + sA*64 + i);
                const float cB = __ldg(fc + sB*64 + i), snB = __ldg(fs + sB*64 + i);
                float r_  = acc[mi][ni][0]*cA - acc[mi][ni][1]*snA;
                float i_  = acc[mi][ni][0]*snA + acc[mi][ni][1]*cA;
                float r2_ = acc[mi][ni][2]*cB - acc[mi][ni][3]*snB;
                float i2_ = acc[mi][ni][2]*snB + acc[mi][ni][3]*cB;
                __nv_bfloat162 lo, lo2;
                __nv_bfloat162 hi  = split_pair(r_,  i_,  &lo);
                __nv_bfloat162 hi2 = split_pair(r2_, i2_, &lo2);
                *(__nv_bfloat162*)(OH + (size_t)r0*N + c0)       = hi;
                *(__nv_bfloat162*)(OL + (size_t)r0*N + c0)       = lo;
                *(__nv_bfloat162*)(OH + (size_t)(r0 + 8)*N + c0) = hi2;
                *(__nv_bfloat162*)(OL + (size_t)(r0 + 8)*N + c0) = lo2;
            }
        }
    } else { // EPI_VT: stage fp32 tile, transpose, split
        __syncthreads();
        float* ct = (float*)smem;    // [128][132]
        #pragma unroll
        for (int mi = 0; mi < 4; mi++) {
            const int r0 = wm*64 + mi*16 + (lane >> 2);
            #pragma unroll
            for (int ni = 0; ni < 4; ni++) {
                const int c0 = wn*32 + ni*8 + (lane & 3)*2;
                ct[(size_t)r0*132 + c0]       = acc[mi][ni][0];
                ct[(size_t)r0*132 + c0 + 1]   = acc[mi][ni][1];
                ct[(size_t)(r0+8)*132 + c0]   = acc[mi][ni][2];
                ct[(size_t)(r0+8)*132 + c0+1] = acc[mi][ni][3];
            }
        }
        __syncthreads();
        const int b  = rowBase >> 10;
        const int s0 = rowBase & (S_ - 1);
        const int hk = colBase >> 7;
        const int d  = tid >> 1;
        const int sh = (tid & 1) * 64;
        __nv_bfloat16* dh = OH + ((size_t)(b*HKV_ + hk)*HD_ + d)*S_ + s0 + sh;
        __nv_bfloat16* dl = OL + ((size_t)(b*HKV_ + hk)*HD_ + d)*S_ + s0 + sh;
        #pragma unroll
        for (int i = 0; i < 64; i += 4) {
            float v0 = ct[(size_t)(sh+i+0)*132 + d];
            float v1 = ct[(size_t)(sh+i+1)*132 + d];
            float v2 = ct[(size_t)(sh+i+2)*132 + d];
            float v3 = ct[(size_t)(sh+i+3)*132 + d];
            __nv_bfloat162 l01, l23;
            __nv_bfloat162 h01 = split_pair(v0, v1, &l01);
            __nv_bfloat162 h23 = split_pair(v2, v3, &l23);
            uint2 hp = make_uint2(*(uint32_t*)&h01, *(uint32_t*)&h23);
            uint2 lp = make_uint2(*(uint32_t*)&l01, *(uint32_t*)&l23);
            *(uint2*)(dh + i) = hp;
            *(uint2*)(dl + i) = lp;
        }
    }
}

// ---------------------------------------------------------------------------
// fp32 -> (hi, lo) bf16 split
// ---------------------------------------------------------------------------
__global__ void split_fp32(const float* __restrict__ in,
                           __nv_bfloat16* __restrict__ hi,
                           __nv_bfloat16* __restrict__ lo, int n)
{
    int i = (blockIdx.x * blockDim.x + threadIdx.x) << 2;
    if (i >= n) return;
    float4 v = *(const float4*)(in + i);
    __nv_bfloat162 l01, l23;
    __nv_bfloat162 h01 = split_pair(v.x, v.y, &l01);
    __nv_bfloat162 h23 = split_pair(v.z, v.w, &l23);
    ((__nv_bfloat162*)(hi + i))[0] = h01;
    ((__nv_bfloat162*)(hi + i))[1] = h23;
    ((__nv_bfloat162*)(lo + i))[0] = l01;
    ((__nv_bfloat162*)(lo + i))[1] = l23;
}

// ---------------------------------------------------------------------------
// w[K,N] fp32 -> [N,K] bf16 hi/lo (transpose + split)
// ---------------------------------------------------------------------------
__global__ void __launch_bounds__(256) transpose_split(const float* __restrict__ w,
                                                       __nv_bfloat16* __restrict__ thi,
                                                       __nv_bfloat16* __restrict__ tlo,
                                                       int K, int N)
{
    __shared__ float t[32][33];
    const int tid = threadIdx.x;
    const int tx = tid & 31, ty = tid >> 5;
    const int n0 = blockIdx.x * 32, k0 = blockIdx.y * 32;
    #pragma unroll
    for (int r = 0; r < 4; r++)
        t[ty + r*8][tx] = w[(size_t)(k0 + ty + r*8) * N + n0 + tx];
    __syncthreads();
    #pragma unroll
    for (int r = 0; r < 4; r++) {
        float v = t[tx][ty + r*8];
        __nv_bfloat16 h = __float2bfloat16(v);
        __nv_bfloat16 l = __float2bfloat16(v - __bfloat162float(h));
        size_t o = (size_t)(n0 + ty + r*8) * K + k0 + tx;
        thi[o] = h;
        tlo[o] = l;
    }
}

// ---------------------------------------------------------------------------
// Flash attention, bf16 mma.sync hi/lo; epilogue writes bf16 hi/lo.
// Grid (S/128, H, B), block 256.
// ---------------------------------------------------------------------------
#define AT_STAGE 65536
#define AT_SMEM  (65536 + 2*AT_STAGE + 128)

__global__ void __launch_bounds__(256, 1) attn_mma(const __nv_bfloat16* __restrict__ qh,
                                                   const __nv_bfloat16* __restrict__ ql,
                                                   const __nv_bfloat16* __restrict__ kh,
                                                   const __nv_bfloat16* __restrict__ kl,
                                                   const __nv_bfloat16* __restrict__ vth,
                                                   const __nv_bfloat16* __restrict__ vtl,
                                                   __nv_bfloat16* __restrict__ Oh,
                                                   __nv_bfloat16* __restrict__ Ol)
{
    extern __shared__ char smem[];
    const uint32_t base = (smem_u32(smem) + 127u) & ~127u;
    const int tid  = threadIdx.x;
    const int lane = tid & 31;
    const int w    = tid >> 5;
    const int q0   = blockIdx.x * 128;
    const int h    = blockIdx.y;
    const int b    = blockIdx.z;
    const int hk   = h >> 2;
    const float scale = 0.08838834764831845f;

    #pragma unroll
    for (int i = 0; i < 8; i++) {
        const int flat = tid + i*256;
        const int c = flat >> 10;
        const int r = (flat >> 3) & 127;
        const int u = flat & 7;
        const size_t src = (size_t)(b*S_ + q0 + r)*D_ + h*HD_ + c*64 + u*8;
        const uint32_t dst = base + c*16384 + SW128((uint32_t)(r*128 + u*16));
        CP16(dst, qh + src);
        CP16(dst + 32768, ql + src);
    }
    CP_COMMIT();

    #define LOAD_KV(t) do {                                                        \
        const uint32_t _sb = base + 65536 + ((t) & 1)*AT_STAGE;                    \
        const int _kv0 = (t) * 64;                                                 \
        _Pragma("unroll")                                                          \
        for (int _i = 0; _i < 4; _i++) {                                           \
            const int _f = tid + _i*256;                                           \
            const int _c = _f >> 9;                                                \
            const int _r = (_f >> 3) & 63;                                         \
            const int _u = _f & 7;                                                 \
            const size_t _src = (size_t)(b*S_ + _kv0 + _r)*KVD_ + hk*HD_ + _c*64 + _u*8; \
            const uint32_t _d = _sb + _c*8192 + SW128((uint32_t)(_r*128 + _u*16)); \
            CP16(_d,          kh + _src);                                          \
            CP16(_d + 16384,  kl + _src);                                          \
        }                                                                          \
        _Pragma("unroll")                                                          \
        for (int _i = 0; _i < 4; _i++) {                                           \
            const int _f = tid + _i*256;                                           \
            const int _r = _f >> 3;                                                \
            const int _u = _f & 7;                                                 \
            const size_t _src = ((size_t)(b*HKV_ + hk)*HD_ + _r)*S_ + _kv0 + _u*8; \
            const uint32_t _d = _sb + 32768 + SW128((uint32_t)(_r*128 + _u*16));   \
            CP16(_d,          vth + _src);                                         \
            CP16(_d + 16384,  vtl + _src);                                         \
        }                                                                          \
        CP_COMMIT();                                                               \
    } while (0)

    LOAD_KV(0);
    LOAD_KV(1);

    float acc_o[16][4];
    #pragma unroll
    for (int t8 = 0; t8 < 16; t8++)
        #pragma unroll
        for (int r = 0; r < 4; r++) acc_o[t8][r] = 0.f;
    float m1 = -INFINITY, m2 = -INFINITY, l1 = 0.f, l2 = 0.f;

    const uint32_t rowA = (uint32_t)((w*16 + (lane & 15)) * 128);

    for (int t = 0; t < S_/64; t++) {
        if (t == S_/64 - 1) asm volatile("cp.async.wait_group 0;" ::: "memory");
        else                asm volatile("cp.async.wait_group 1;" ::: "memory");
        __syncthreads();

        const uint32_t sb = base + 65536 + (t & 1)*AT_STAGE;

        float sa[8][4];
        #pragma unroll
        for (int t8 = 0; t8 < 8; t8++)
            #pragma unroll
            for (int r = 0; r < 4; r++) sa[t8][r] = 0.f;

        #pragma unroll
        for (int ks = 0; ks < 8; ks++) {
            const int chunk = ks >> 2;
            const uint32_t kb = (uint32_t)((ks & 3)*32 + (lane >> 4)*16);
            uint32_t qah[4], qal[4];
            const uint32_t swA = SW128(rowA + kb);
            LDSM4(qah[0], qah[1], qah[2], qah[3], base + chunk*16384 + swA);
            LDSM4(qal[0], qal[1], qal[2], qal[3], base + 32768 + chunk*16384 + swA);
            #pragma unroll
            for (int nj = 0; nj < 4; nj++) {
                const uint32_t sw = SW128((uint32_t)((nj*16 + (lane & 15))*128) + kb);
                uint32_t k0h[2], k1h[2], k0l[2], k1l[2];
                LDSM4(k0h[0], k1h[0], k0h[1], k1h[1], sb + chunk*8192 + sw);
                LDSM4(k0l[0], k1l[0], k0l[1], k1l[1], sb + 16384 + chunk*8192 + sw);
                MMA_BF16(sa[2*nj],   qah, k0h);
                MMA_BF16(sa[2*nj],   qah, k0l);
                MMA_BF16(sa[2*nj],   qal, k0h);
                MMA_BF16(sa[2*nj+1], qah, k1h);
                MMA_BF16(sa[2*nj+1], qah, k1l);
                MMA_BF16(sa[2*nj+1], qal, k1h);
            }
        }

        float mx1 = -INFINITY, mx2 = -INFINITY;
        #pragma unroll
        for (int t8 = 0; t8 < 8; t8++) {
            mx1 = fmaxf(mx1, fmaxf(sa[t8][0], sa[t8][1]));
            mx2 = fmaxf(mx2, fmaxf(sa[t8][2], sa[t8][3]));
        }
        mx1 *= scale; mx2 *= scale;
        mx1 = fmaxf(mx1, __shfl_xor_sync(0xFFFFFFFFu, mx1, 1));
        mx1 = fmaxf(mx1, __shfl_xor_sync(0xFFFFFFFFu, mx1, 2));
        mx2 = fmaxf(mx2, __shfl_xor_sync(0xFFFFFFFFu, mx2, 1));
        mx2 = fmaxf(mx2, __shfl_xor_sync(0xFFFFFFFFu, mx2, 2));
        const float mn1 = fmaxf(m1, mx1), mn2 = fmaxf(m2, mx2);
        const float al1 = __expf(m1 - mn1), al2 = __expf(m2 - mn2);

        uint32_t Ph[4][4], Pl[4][4];
        float sum1 = 0.f, sum2 = 0.f;
        #pragma unroll
        for (int t8 = 0; t8 < 8; t8++) {
            const float p0 = __expf(sa[t8][0]*scale - mn1);
            const float p1 = __expf(sa[t8][1]*scale - mn1);
            const float p2 = __expf(sa[t8][2]*scale - mn2);
            const float p3 = __expf(sa[t8][3]*scale - mn2);
            sum1 += p0 + p1; sum2 += p2 + p3;
            __nv_bfloat162 l01, l23;
            __nv_bfloat162 h01 = split_pair(p0, p1, &l01);
            __nv_bfloat162 h23 = split_pair(p2, p3, &l23);
            const int j = t8 >> 1;
            const int o = (t8 & 1) ? 2 : 0;
            Ph[j][o]     = *(uint32_t*)&h01;
            Ph[j][o + 1] = *(uint32_t*)&h23;
            Pl[j][o]     = *(uint32_t*)&l01;
            Pl[j][o + 1] = *(uint32_t*)&l23;
        }
        sum1 += __shfl_xor_sync(0xFFFFFFFFu, sum1, 1);
        sum1 += __shfl_xor_sync(0xFFFFFFFFu, sum1, 2);
        sum2 += __shfl_xor_sync(0xFFFFFFFFu, sum2, 1);
        sum2 += __shfl_xor_sync(0xFFFFFFFFu, sum2, 2);
        l1 = l1*al1 + sum1;  m1 = mn1;
        l2 = l2*al2 + sum2;  m2 = mn2;

        #pragma unroll
        for (int t8 = 0; t8 < 16; t8++) {
            acc_o[t8][0] *= al1; acc_o[t8][1] *= al1;
            acc_o[t8][2] *= al2; acc_o[t8][3] *= al2;
        }

        #pragma unroll
        for (int j = 0; j < 4; j++) {
            const uint32_t kb = (uint32_t)(j*32 + (lane >> 4)*16);
            #pragma unroll
            for (int nj = 0; nj < 8; nj++) {
                const uint32_t sw = SW128((uint32_t)((nj*16 + (lane & 15))*128) + kb);
                uint32_t v0h[2], v1h[2], v0l[2], v1l[2];
                LDSM4(v0h[0], v1h[0], v0h[1], v1h[1], sb + 32768 + sw);
                LDSM4(v0l[0], v1l[0], v0l[1], v1l[1], sb + 49152 + sw);
                MMA_BF16(acc_o[2*nj],   Ph[j], v0h);
                MMA_BF16(acc_o[2*nj],   Ph[j], v0l);
                MMA_BF16(acc_o[2*nj],   Pl[j], v0h);
                MMA_BF16(acc_o[2*nj+1], Ph[j], v1h);
                MMA_BF16(acc_o[2*nj+1], Ph[j], v1l);
                MMA_BF16(acc_o[2*nj+1], Pl[j], v1h);
            }
        }

        __syncthreads();
        if (t + 2 < S_/64) LOAD_KV(t + 2);
    }

    const float inv1 = 1.f / l1, inv2 = 1.f / l2;
    const int r1 = q0 + w*16 + (lane >> 2);
    #pragma unroll
    for (int t8 = 0; t8 < 16; t8++) {
        const int c = h*HD_ + t8*8 + (lane & 3)*2;
        __nv_bfloat162 lo1, lo2;
        __nv_bfloat162 hi1 = split_pair(acc_o[t8][0]*inv1, acc_o[t8][1]*inv1, &lo1);
        __nv_bfloat162 hi2 = split_pair(acc_o[t8][2]*inv2, acc_o[t8][3]*inv2, &lo2);
        *(__nv_bfloat162*)(Oh + (size_t)(b*S_ + r1)*D_ + c)     = hi1;
        *(__nv_bfloat162*)(Ol + (size_t)(b*S_ + r1)*D_ + c)     = lo1;
        *(__nv_bfloat162*)(Oh + (size_t)(b*S_ + r1 + 8)*D_ + c) = hi2;
        *(__nv_bfloat162*)(Ol + (size_t)(b*S_ + r1 + 8)*D_ + c) = lo2;
    }
    #undef LOAD_KV
}

// ---------------------------------------------------------------------------
// Launch
// ---------------------------------------------------------------------------
extern "C" void kernel_launch(void* const* d_in, const int* in_sizes, int n_in,
                              void* d_out, int out_size)
{
    const float* x  = (const float*)d_in[0];
    const float* fc = (const float*)d_in[1];
    const float* fs = (const float*)d_in[2];
    const float* wq = (const float*)d_in[3];
    const float* wk = (const float*)d_in[4];
    const float* wv = (const float*)d_in[5];
    const float* wo = (const float*)d_in[6];
    float* out = (float*)d_out;

    __nv_bfloat16 *xh, *xl, *qh, *ql, *kh, *kl, *vth, *vtl, *oh, *ol;
    __nv_bfloat16 *wqh, *wql, *wkh, *wkl, *wvh, *wvl, *woh, *wol;
    cudaGetSymbolAddress((void**)&xh,  g_xh);
    cudaGetSymbolAddress((void**)&xl,  g_xl);
    cudaGetSymbolAddress((void**)&qh,  g_qh);
    cudaGetSymbolAddress((void**)&ql,  g_ql);
    cudaGetSymbolAddress((void**)&kh,  g_kh);
    cudaGetSymbolAddress((void**)&kl,  g_kl);
    cudaGetSymbolAddress((void**)&vth, g_vth);
    cudaGetSymbolAddress((void**)&vtl, g_vtl);
    cudaGetSymbolAddress((void**)&oh,  g_oh);
    cudaGetSymbolAddress((void**)&ol,  g_ol);
    cudaGetSymbolAddress((void**)&wqh, g_wqh);
    cudaGetSymbolAddress((void**)&wql, g_wql);
    cudaGetSymbolAddress((void**)&wkh, g_wkh);
    cudaGetSymbolAddress((void**)&wkl, g_wkl);
    cudaGetSymbolAddress((void**)&wvh, g_wvh);
    cudaGetSymbolAddress((void**)&wvl, g_wvl);
    cudaGetSymbolAddress((void**)&woh, g_woh);
    cudaGetSymbolAddress((void**)&wol, g_wol);

    cudaFuncSetAttribute(gemm_tc<EPI_PLAIN>, cudaFuncAttributeMaxDynamicSharedMemorySize, GEMM_SMEM);
    cudaFuncSetAttribute(gemm_tc<EPI_ROPE>,  cudaFuncAttributeMaxDynamicSharedMemorySize, GEMM_SMEM);
    cudaFuncSetAttribute(gemm_tc<EPI_VT>,    cudaFuncAttributeMaxDynamicSharedMemorySize, GEMM_SMEM);
    cudaFuncSetAttribute(attn_mma, cudaFuncAttributeMaxDynamicSharedMemorySize, AT_SMEM);

    // 1) conversions
    split_fp32<<<(M_*D_/4 + 255)/256, 256>>>(x, xh, xl, M_*D_);
    transpose_split<<<dim3(D_/32,   D_/32), 256>>>(wq, wqh, wql, D_, D_);
    transpose_split<<<dim3(KVD_/32, D_/32), 256>>>(wk, wkh, wkl, D_, KVD_);
    transpose_split<<<dim3(KVD_/32, D_/32), 256>>>(wv, wvh, wvl, D_, KVD_);
    transpose_split<<<dim3(D_/32,   D_/32), 256>>>(wo, woh, wol, D_, D_);

    // 2) QKV projections with fused RoPE/split/transpose epilogues
    gemm_tc<EPI_ROPE><<<dim3(D_/128,   M_/128), 256, GEMM_SMEM>>>(xh, xl, wqh, wql,
        nullptr, qh, ql, fc, fs, D_, D_);
    gemm_tc<EPI_ROPE><<<dim3(KVD_/128, M_/128), 256, GEMM_SMEM>>>(xh, xl, wkh, wkl,
        nullptr, kh, kl, fc, fs, KVD_, D_);
    gemm_tc<EPI_VT><<<dim3(KVD_/128,   M_/128), 256, GEMM_SMEM>>>(xh, xl, wvh, wvl,
        nullptr, vth, vtl, nullptr, nullptr, KVD_, D_);

    // 3) attention (tensor-core flash; epilogue split)
    attn_mma<<<dim3(S_/128, H_, B_), 256, AT_SMEM>>>(qh, ql, kh, kl, vth, vtl, oh, ol);

    // 4) output projection
    gemm_tc<EPI_PLAIN><<<dim3(D_/128, M_/128), 256, GEMM_SMEM>>>(oh, ol, woh, wol,
        out, nullptr, nullptr, nullptr, nullptr, D_, D_);
}

// round 7
// speedup vs baseline: 1.0471x; 1.0471x over previous
#include <cuda_runtime.h>
#include <cuda_bf16.h>
#include <math.h>
#include <cstdint>

#define B_    4
#define S_    1024
#define D_    4096
#define H_    32
#define HKV_  8
#define HD_   128
#define KVD_  (HKV_*HD_)   // 1024
#define M_    (B_*S_)      // 4096
#define NQKV  (D_ + 2*KVD_)  // 6144

// ---------------- scratch (static device globals) ----------------
__device__ __nv_bfloat16 g_xh[M_*D_],  g_xl[M_*D_];     // x split
__device__ __nv_bfloat16 g_qh[M_*D_],  g_ql[M_*D_];     // rope(Q)
__device__ __nv_bfloat16 g_kh[M_*KVD_], g_kl[M_*KVD_];  // rope(K)
__device__ __nv_bfloat16 g_vth[M_*KVD_], g_vtl[M_*KVD_];// V^T [b][hk][d][s]
__device__ __nv_bfloat16 g_oh[M_*D_],  g_ol[M_*D_];     // attn out split
__device__ __nv_bfloat16 g_wh[NQKV*D_], g_wl[NQKV*D_];  // [wq|wk|wv]^T rows
__device__ __nv_bfloat16 g_woh[D_*D_],  g_wol[D_*D_];

// ---------------- PTX helpers ----------------
__device__ __forceinline__ uint32_t smem_u32(const void* p) {
    uint32_t a;
    asm("{ .reg .u64 t; cvta.to.shared.u64 t, %1; cvt.u32.u64 %0, t; }" : "=r"(a) : "l"(p));
    return a;
}
#define SW128(off) ((off) ^ (((off) >> 3) & 0x70))
#define CP16(dst, src) asm volatile("cp.async.cg.shared.global [%0], [%1], 16;" :: "r"(dst), "l"(src))
#define CP_COMMIT()    asm volatile("cp.async.commit_group;" ::: "memory")
#define LDSM4(r0, r1, r2, r3, a)                                             \
    asm volatile("ldmatrix.sync.aligned.m8n8.x4.shared.b16 {%0,%1,%2,%3}, [%4];" \
        : "=r"(r0), "=r"(r1), "=r"(r2), "=r"(r3) : "r"(a))
#define MMA_BF16(ac, ar, br)                                                 \
    asm volatile("mma.sync.aligned.m16n8k16.row.col.f32.bf16.bf16.f32 "      \
        "{%0,%1,%2,%3}, {%4,%5,%6,%7}, {%8,%9}, {%0,%1,%2,%3};"              \
        : "+f"((ac)[0]), "+f"((ac)[1]), "+f"((ac)[2]), "+f"((ac)[3])         \
        : "r"((ar)[0]), "r"((ar)[1]), "r"((ar)[2]), "r"((ar)[3]),            \
          "r"((br)[0]), "r"((br)[1]))

__device__ __forceinline__ __nv_bfloat162 split_pair(float a, float b,
                                                     __nv_bfloat162* lo) {
    __nv_bfloat162 h = __floats2bfloat162_rn(a, b);
    *lo = __floats2bfloat162_rn(a - __bfloat162float(h.x), b - __bfloat162float(h.y));
    return h;
}

// ---------------------------------------------------------------------------
// Warp-MMA GEMM mainloop (shared): acc += (Ah+Al) @ (Bh+Bl)^T on a 128x128
// tile; term-major MMA ordering to break accumulator RAW chains.
// ---------------------------------------------------------------------------
#define STAGE_BYTES 65536
#define GEMM_SMEM  (3*STAGE_BYTES + 128)

__device__ __forceinline__ void gemm_mainloop(const __nv_bfloat16* Ah,
                                              const __nv_bfloat16* Al,
                                              const __nv_bfloat16* Bh,
                                              const __nv_bfloat16* Bl,
                                              uint32_t base, int rowBase, int colBase,
                                              int K, float acc[4][4][4])
{
    const int tid  = threadIdx.x;
    const int lane = tid & 31;
    const int wid  = tid >> 5;
    const int wm   = wid & 1;
    const int wn   = wid >> 1;
    const int nc = K >> 6;

    #define LOAD_CHUNK(c) do {                                                     \
        const int _s = (c) % 3;                                                    \
        const uint32_t _st = base + _s*STAGE_BYTES;                                \
        const int _kb = (c) * 64;                                                  \
        _Pragma("unroll")                                                          \
        for (int _i = 0; _i < 4; _i++) {                                           \
            const int _id  = tid + _i*256;                                         \
            const int _row = _id >> 3;                                             \
            const int _u   = _id & 7;                                              \
            const uint32_t _sw = SW128((uint32_t)(_row*128 + _u*16));              \
            const size_t _ao = (size_t)(rowBase + _row)*K + _kb + _u*8;            \
            const size_t _bo = (size_t)(colBase + _row)*K + _kb + _u*8;            \
            CP16(_st +         _sw, Ah + _ao);                                     \
            CP16(_st + 16384 + _sw, Al + _ao);                                     \
            CP16(_st + 32768 + _sw, Bh + _bo);                                     \
            CP16(_st + 49152 + _sw, Bl + _bo);                                     \
        }                                                                          \
        CP_COMMIT();                                                               \
    } while (0)

    LOAD_CHUNK(0); LOAD_CHUNK(1);

    for (int c = 0; c < nc; c++) {
        if (c == nc - 1) asm volatile("cp.async.wait_group 0;" ::: "memory");
        else             asm volatile("cp.async.wait_group 1;" ::: "memory");
        __syncthreads();
        if (c + 2 < nc) LOAD_CHUNK(c + 2);

        const uint32_t stA  = base + (c % 3)*STAGE_BYTES;
        const uint32_t stAl = stA + 16384;
        const uint32_t stB  = stA + 32768;
        const uint32_t stBl = stA + 49152;

        #pragma unroll
        for (int ks = 0; ks < 4; ks++) {
            const uint32_t kb = (uint32_t)(ks*32 + (lane >> 4)*16);

            uint32_t ah[4][4], al4[4][4];
            #pragma unroll
            for (int mi = 0; mi < 4; mi++) {
                const uint32_t off = (uint32_t)((wm*64 + mi*16 + (lane & 15)) * 128) + kb;
                const uint32_t sw  = SW128(off);
                LDSM4(ah[mi][0],  ah[mi][1],  ah[mi][2],  ah[mi][3],  stA  + sw);
                LDSM4(al4[mi][0], al4[mi][1], al4[mi][2], al4[mi][3], stAl + sw);
            }
            uint32_t bh[4][2], bl4[4][2];
            #pragma unroll
            for (int nj = 0; nj < 2; nj++) {
                const uint32_t off = (uint32_t)((wn*32 + nj*16 + (lane & 15)) * 128) + kb;
                const uint32_t sw  = SW128(off);
                LDSM4(bh[2*nj][0],  bh[2*nj+1][0],  bh[2*nj][1],  bh[2*nj+1][1],  stB  + sw);
                LDSM4(bl4[2*nj][0], bl4[2*nj+1][0], bl4[2*nj][1], bl4[2*nj+1][1], stBl + sw);
            }

            // term-major: 16 independent accs between same-acc reuses
            #pragma unroll
            for (int mi = 0; mi < 4; mi++)
                #pragma unroll
                for (int ni = 0; ni < 4; ni++)
                    MMA_BF16(acc[mi][ni], ah[mi],  bh[ni]);
            #pragma unroll
            for (int mi = 0; mi < 4; mi++)
                #pragma unroll
                for (int ni = 0; ni < 4; ni++)
                    MMA_BF16(acc[mi][ni], ah[mi],  bl4[ni]);
            #pragma unroll
            for (int mi = 0; mi < 4; mi++)
                #pragma unroll
                for (int ni = 0; ni < 4; ni++)
                    MMA_BF16(acc[mi][ni], al4[mi], bh[ni]);
        }
    }
    #undef LOAD_CHUNK
}

// ---------------------------------------------------------------------------
// Fused QKV GEMM: A=[M,4096] x Wqkv^T[6144,4096]; epilogue by column range:
// cols [0,4096) ropeQ -> qh/ql; [4096,5120) ropeK -> kh/kl; [5120,6144) V^T.
// Grid (48, 32), block 256.
// ---------------------------------------------------------------------------
__global__ void __launch_bounds__(256, 1) gemm_qkv(const __nv_bfloat16* __restrict__ Ah,
                                                   const __nv_bfloat16* __restrict__ Al,
                                                   const __nv_bfloat16* __restrict__ Bh,
                                                   const __nv_bfloat16* __restrict__ Bl,
                                                   __nv_bfloat16* __restrict__ qh,
                                                   __nv_bfloat16* __restrict__ ql,
                                                   __nv_bfloat16* __restrict__ kh,
                                                   __nv_bfloat16* __restrict__ kl,
                                                   __nv_bfloat16* __restrict__ vth,
                                                   __nv_bfloat16* __restrict__ vtl,
                                                   const float* __restrict__ fc,
                                                   const float* __restrict__ fs)
{
    extern __shared__ char smem[];
    const uint32_t base = (smem_u32(smem) + 127u) & ~127u;
    const int tid  = threadIdx.x;
    const int lane = tid & 31;
    const int wid  = tid >> 5;
    const int wm   = wid & 1;
    const int wn   = wid >> 1;
    const int rowBase = blockIdx.y * 128;
    const int colBase = blockIdx.x * 128;

    float acc[4][4][4];
    #pragma unroll
    for (int mi = 0; mi < 4; mi++)
        #pragma unroll
        for (int ni = 0; ni < 4; ni++)
            #pragma unroll
            for (int r = 0; r < 4; r++) acc[mi][ni][r] = 0.f;

    gemm_mainloop(Ah, Al, Bh, Bl, base, rowBase, colBase, D_, acc);

    if (colBase < D_ + KVD_) {
        // RoPE epilogue (Q if colBase<4096 else K)
        __nv_bfloat16* OH;
        __nv_bfloat16* OL;
        int N, cb;
        if (colBase < D_) { OH = qh; OL = ql; N = D_;   cb = colBase; }
        else              { OH = kh; OL = kl; N = KVD_; cb = colBase - D_; }
        #pragma unroll
        for (int mi = 0; mi < 4; mi++) {
            const int r0 = rowBase + wm*64 + mi*16 + (lane >> 2);
            const int sA = r0 & (S_ - 1);
            const int sB = (r0 + 8) & (S_ - 1);
            #pragma unroll
            for (int ni = 0; ni < 4; ni++) {
                const int c0 = cb + wn*32 + ni*8 + (lane & 3)*2;
                const int i  = (c0 & 127) >> 1;
                const float cA = __ldg(fc + sA*64 + i), snA = __ldg(fs + sA*64 + i);
                const float cB = __ldg(fc + sB*64 + i), snB = __ldg(fs + sB*64 + i);
                float r_  = acc[mi][ni][0]*cA - acc[mi][ni][1]*snA;
                float i_  = acc[mi][ni][0]*snA + acc[mi][ni][1]*cA;
                float r2_ = acc[mi][ni][2]*cB - acc[mi][ni][3]*snB;
                float i2_ = acc[mi][ni][2]*snB + acc[mi][ni][3]*cB;
                __nv_bfloat162 lo, lo2;
                __nv_bfloat162 hi  = split_pair(r_,  i_,  &lo);
                __nv_bfloat162 hi2 = split_pair(r2_, i2_, &lo2);
                *(__nv_bfloat162*)(OH + (size_t)r0*N + c0)       = hi;
                *(__nv_bfloat162*)(OL + (size_t)r0*N + c0)       = lo;
                *(__nv_bfloat162*)(OH + (size_t)(r0 + 8)*N + c0) = hi2;
                *(__nv_bfloat162*)(OL + (size_t)(r0 + 8)*N + c0) = lo2;
            }
        }
    } else {
        // V^T epilogue: stage fp32 tile, transpose, split
        __syncthreads();
        float* ct = (float*)smem;    // [128][132]
        #pragma unroll
        for (int mi = 0; mi < 4; mi++) {
            const int r0 = wm*64 + mi*16 + (lane >> 2);
            #pragma unroll
            for (int ni = 0; ni < 4; ni++) {
                const int c0 = wn*32 + ni*8 + (lane & 3)*2;
                ct[(size_t)r0*132 + c0]       = acc[mi][ni][0];
                ct[(size_t)r0*132 + c0 + 1]   = acc[mi][ni][1];
                ct[(size_t)(r0+8)*132 + c0]   = acc[mi][ni][2];
                ct[(size_t)(r0+8)*132 + c0+1] = acc[mi][ni][3];
            }
        }
        __syncthreads();
        const int b  = rowBase >> 10;
        const int s0 = rowBase & (S_ - 1);
        const int hk = (colBase - D_ - KVD_) >> 7;
        const int d  = tid >> 1;
        const int sh = (tid & 1) * 64;
        __nv_bfloat16* dh = vth + ((size_t)(b*HKV_ + hk)*HD_ + d)*S_ + s0 + sh;
        __nv_bfloat16* dl = vtl + ((size_t)(b*HKV_ + hk)*HD_ + d)*S_ + s0 + sh;
        #pragma unroll
        for (int i = 0; i < 64; i += 4) {
            float v0 = ct[(size_t)(sh+i+0)*132 + d];
            float v1 = ct[(size_t)(sh+i+1)*132 + d];
            float v2 = ct[(size_t)(sh+i+2)*132 + d];
            float v3 = ct[(size_t)(sh+i+3)*132 + d];
            __nv_bfloat162 l01, l23;
            __nv_bfloat162 h01 = split_pair(v0, v1, &l01);
            __nv_bfloat162 h23 = split_pair(v2, v3, &l23);
            *(uint2*)(dh + i) = make_uint2(*(uint32_t*)&h01, *(uint32_t*)&h23);
            *(uint2*)(dl + i) = make_uint2(*(uint32_t*)&l01, *(uint32_t*)&l23);
        }
    }
}

// ---------------------------------------------------------------------------
// Output-projection GEMM: plain fp32 epilogue.
// ---------------------------------------------------------------------------
__global__ void __launch_bounds__(256, 1) gemm_wo(const __nv_bfloat16* __restrict__ Ah,
                                                  const __nv_bfloat16* __restrict__ Al,
                                                  const __nv_bfloat16* __restrict__ Bh,
                                                  const __nv_bfloat16* __restrict__ Bl,
                                                  float* __restrict__ C)
{
    extern __shared__ char smem[];
    const uint32_t base = (smem_u32(smem) + 127u) & ~127u;
    const int tid  = threadIdx.x;
    const int lane = tid & 31;
    const int wid  = tid >> 5;
    const int wm   = wid & 1;
    const int wn   = wid >> 1;
    const int rowBase = blockIdx.y * 128;
    const int colBase = blockIdx.x * 128;

    float acc[4][4][4];
    #pragma unroll
    for (int mi = 0; mi < 4; mi++)
        #pragma unroll
        for (int ni = 0; ni < 4; ni++)
            #pragma unroll
            for (int r = 0; r < 4; r++) acc[mi][ni][r] = 0.f;

    gemm_mainloop(Ah, Al, Bh, Bl, base, rowBase, colBase, D_, acc);

    #pragma unroll
    for (int mi = 0; mi < 4; mi++) {
        const int r0 = rowBase + wm*64 + mi*16 + (lane >> 2);
        #pragma unroll
        for (int ni = 0; ni < 4; ni++) {
            const int c0 = colBase + wn*32 + ni*8 + (lane & 3)*2;
            *(float2*)(C + (size_t)r0*D_ + c0)       = make_float2(acc[mi][ni][0], acc[mi][ni][1]);
            *(float2*)(C + (size_t)(r0 + 8)*D_ + c0) = make_float2(acc[mi][ni][2], acc[mi][ni][3]);
        }
    }
}

// ---------------------------------------------------------------------------
// fp32 -> (hi, lo) bf16 split
// ---------------------------------------------------------------------------
__global__ void split_fp32(const float* __restrict__ in,
                           __nv_bfloat16* __restrict__ hi,
                           __nv_bfloat16* __restrict__ lo, int n)
{
    int i = (blockIdx.x * blockDim.x + threadIdx.x) << 2;
    if (i >= n) return;
    float4 v = *(const float4*)(in + i);
    __nv_bfloat162 l01, l23;
    __nv_bfloat162 h01 = split_pair(v.x, v.y, &l01);
    __nv_bfloat162 h23 = split_pair(v.z, v.w, &l23);
    ((__nv_bfloat162*)(hi + i))[0] = h01;
    ((__nv_bfloat162*)(hi + i))[1] = h23;
    ((__nv_bfloat162*)(lo + i))[0] = l01;
    ((__nv_bfloat162*)(lo + i))[1] = l23;
}

// ---------------------------------------------------------------------------
// w[K,N] fp32 -> [N,K] bf16 hi/lo (transpose + split)
// ---------------------------------------------------------------------------
__global__ void __launch_bounds__(256) transpose_split(const float* __restrict__ w,
                                                       __nv_bfloat16* __restrict__ thi,
                                                       __nv_bfloat16* __restrict__ tlo,
                                                       int K, int N)
{
    __shared__ float t[32][33];
    const int tid = threadIdx.x;
    const int tx = tid & 31, ty = tid >> 5;
    const int n0 = blockIdx.x * 32, k0 = blockIdx.y * 32;
    #pragma unroll
    for (int r = 0; r < 4; r++)
        t[ty + r*8][tx] = w[(size_t)(k0 + ty + r*8) * N + n0 + tx];
    __syncthreads();
    #pragma unroll
    for (int r = 0; r < 4; r++) {
        float v = t[tx][ty + r*8];
        __nv_bfloat16 h = __float2bfloat16(v);
        __nv_bfloat16 l = __float2bfloat16(v - __bfloat162float(h));
        size_t o = (size_t)(n0 + ty + r*8) * K + k0 + tx;
        thi[o] = h;
        tlo[o] = l;
    }
}

// ---------------------------------------------------------------------------
// Flash attention, bf16 mma.sync hi/lo; epilogue writes bf16 hi/lo.
// Grid (S/128, H, B), block 256.
// ---------------------------------------------------------------------------
#define AT_STAGE 65536
#define AT_SMEM  (65536 + 2*AT_STAGE + 128)

__global__ void __launch_bounds__(256, 1) attn_mma(const __nv_bfloat16* __restrict__ qh,
                                                   const __nv_bfloat16* __restrict__ ql,
                                                   const __nv_bfloat16* __restrict__ kh,
                                                   const __nv_bfloat16* __restrict__ kl,
                                                   const __nv_bfloat16* __restrict__ vth,
                                                   const __nv_bfloat16* __restrict__ vtl,
                                                   __nv_bfloat16* __restrict__ Oh,
                                                   __nv_bfloat16* __restrict__ Ol)
{
    extern __shared__ char smem[];
    const uint32_t base = (smem_u32(smem) + 127u) & ~127u;
    const int tid  = threadIdx.x;
    const int lane = tid & 31;
    const int w    = tid >> 5;
    const int q0   = blockIdx.x * 128;
    const int h    = blockIdx.y;
    const int b    = blockIdx.z;
    const int hk   = h >> 2;
    const float scale = 0.08838834764831845f;

    #pragma unroll
    for (int i = 0; i < 8; i++) {
        const int flat = tid + i*256;
        const int c = flat >> 10;
        const int r = (flat >> 3) & 127;
        const int u = flat & 7;
        const size_t src = (size_t)(b*S_ + q0 + r)*D_ + h*HD_ + c*64 + u*8;
        const uint32_t dst = base + c*16384 + SW128((uint32_t)(r*128 + u*16));
        CP16(dst, qh + src);
        CP16(dst + 32768, ql + src);
    }
    CP_COMMIT();

    #define LOAD_KV(t) do {                                                        \
        const uint32_t _sb = base + 65536 + ((t) & 1)*AT_STAGE;                    \
        const int _kv0 = (t) * 64;                                                 \
        _Pragma("unroll")                                                          \
        for (int _i = 0; _i < 4; _i++) {                                           \
            const int _f = tid + _i*256;                                           \
            const int _c = _f >> 9;                                                \
            const int _r = (_f >> 3) & 63;                                         \
            const int _u = _f & 7;                                                 \
            const size_t _src = (size_t)(b*S_ + _kv0 + _r)*KVD_ + hk*HD_ + _c*64 + _u*8; \
            const uint32_t _d = _sb + _c*8192 + SW128((uint32_t)(_r*128 + _u*16)); \
            CP16(_d,          kh + _src);                                          \
            CP16(_d + 16384,  kl + _src);                                          \
        }                                                                          \
        _Pragma("unroll")                                                          \
        for (int _i = 0; _i < 4; _i++) {                                           \
            const int _f = tid + _i*256;                                           \
            const int _r = _f >> 3;                                                \
            const int _u = _f & 7;                                                 \
            const size_t _src = ((size_t)(b*HKV_ + hk)*HD_ + _r)*S_ + _kv0 + _u*8; \
            const uint32_t _d = _sb + 32768 + SW128((uint32_t)(_r*128 + _u*16));   \
            CP16(_d,          vth + _src);                                         \
            CP16(_d + 16384,  vtl + _src);                                         \
        }                                                                          \
        CP_COMMIT();                                                               \
    } while (0)

    LOAD_KV(0);
    LOAD_KV(1);

    float acc_o[16][4];
    #pragma unroll
    for (int t8 = 0; t8 < 16; t8++)
        #pragma unroll
        for (int r = 0; r < 4; r++) acc_o[t8][r] = 0.f;
    float m1 = -INFINITY, m2 = -INFINITY, l1 = 0.f, l2 = 0.f;

    const uint32_t rowA = (uint32_t)((w*16 + (lane & 15)) * 128);

    for (int t = 0; t < S_/64; t++) {
        if (t == S_/64 - 1) asm volatile("cp.async.wait_group 0;" ::: "memory");
        else                asm volatile("cp.async.wait_group 1;" ::: "memory");
        __syncthreads();

        const uint32_t sb = base + 65536 + (t & 1)*AT_STAGE;

        float sa[8][4];
        #pragma unroll
        for (int t8 = 0; t8 < 8; t8++)
            #pragma unroll
            for (int r = 0; r < 4; r++) sa[t8][r] = 0.f;

        #pragma unroll
        for (int ks = 0; ks < 8; ks++) {
            const int chunk = ks >> 2;
            const uint32_t kb = (uint32_t)((ks & 3)*32 + (lane >> 4)*16);
            uint32_t qah[4], qal[4];
            const uint32_t swA = SW128(rowA + kb);
            LDSM4(qah[0], qah[1], qah[2], qah[3], base + chunk*16384 + swA);
            LDSM4(qal[0], qal[1], qal[2], qal[3], base + 32768 + chunk*16384 + swA);
            uint32_t kfh[8][2], kfl[8][2];
            #pragma unroll
            for (int nj = 0; nj < 4; nj++) {
                const uint32_t sw = SW128((uint32_t)((nj*16 + (lane & 15))*128) + kb);
                LDSM4(kfh[2*nj][0], kfh[2*nj+1][0], kfh[2*nj][1], kfh[2*nj+1][1], sb + chunk*8192 + sw);
                LDSM4(kfl[2*nj][0], kfl[2*nj+1][0], kfl[2*nj][1], kfl[2*nj+1][1], sb + 16384 + chunk*8192 + sw);
            }
            #pragma unroll
            for (int j8 = 0; j8 < 8; j8++) MMA_BF16(sa[j8], qah, kfh[j8]);
            #pragma unroll
            for (int j8 = 0; j8 < 8; j8++) MMA_BF16(sa[j8], qah, kfl[j8]);
            #pragma unroll
            for (int j8 = 0; j8 < 8; j8++) MMA_BF16(sa[j8], qal, kfh[j8]);
        }

        float mx1 = -INFINITY, mx2 = -INFINITY;
        #pragma unroll
        for (int t8 = 0; t8 < 8; t8++) {
            mx1 = fmaxf(mx1, fmaxf(sa[t8][0], sa[t8][1]));
            mx2 = fmaxf(mx2, fmaxf(sa[t8][2], sa[t8][3]));
        }
        mx1 *= scale; mx2 *= scale;
        mx1 = fmaxf(mx1, __shfl_xor_sync(0xFFFFFFFFu, mx1, 1));
        mx1 = fmaxf(mx1, __shfl_xor_sync(0xFFFFFFFFu, mx1, 2));
        mx2 = fmaxf(mx2, __shfl_xor_sync(0xFFFFFFFFu, mx2, 1));
        mx2 = fmaxf(mx2, __shfl_xor_sync(0xFFFFFFFFu, mx2, 2));
        const float mn1 = fmaxf(m1, mx1), mn2 = fmaxf(m2, mx2);
        const float al1 = __expf(m1 - mn1), al2 = __expf(m2 - mn2);

        uint32_t Ph[4][4], Pl[4][4];
        float sum1 = 0.f, sum2 = 0.f;
        #pragma unroll
        for (int t8 = 0; t8 < 8; t8++) {
            const float p0 = __expf(sa[t8][0]*scale - mn1);
            const float p1 = __expf(sa[t8][1]*scale - mn1);
            const float p2 = __expf(sa[t8][2]*scale - mn2);
            const float p3 = __expf(sa[t8][3]*scale - mn2);
            sum1 += p0 + p1; sum2 += p2 + p3;
            __nv_bfloat162 l01, l23;
            __nv_bfloat162 h01 = split_pair(p0, p1, &l01);
            __nv_bfloat162 h23 = split_pair(p2, p3, &l23);
            const int j = t8 >> 1;
            const int o = (t8 & 1) ? 2 : 0;
            Ph[j][o]     = *(uint32_t*)&h01;
            Ph[j][o + 1] = *(uint32_t*)&h23;
            Pl[j][o]     = *(uint32_t*)&l01;
            Pl[j][o + 1] = *(uint32_t*)&l23;
        }
        sum1 += __shfl_xor_sync(0xFFFFFFFFu, sum1, 1);
        sum1 += __shfl_xor_sync(0xFFFFFFFFu, sum1, 2);
        sum2 += __shfl_xor_sync(0xFFFFFFFFu, sum2, 1);
        sum2 += __shfl_xor_sync(0xFFFFFFFFu, sum2, 2);
        l1 = l1*al1 + sum1;  m1 = mn1;
        l2 = l2*al2 + sum2;  m2 = mn2;

        #pragma unroll
        for (int t8 = 0; t8 < 16; t8++) {
            acc_o[t8][0] *= al1; acc_o[t8][1] *= al1;
            acc_o[t8][2] *= al2; acc_o[t8][3] *= al2;
        }

        #pragma unroll
        for (int j = 0; j < 4; j++) {
            const uint32_t kb = (uint32_t)(j*32 + (lane >> 4)*16);
            uint32_t vfh[16][2], vfl[16][2];
            #pragma unroll
            for (int nj = 0; nj < 8; nj++) {
                const uint32_t sw = SW128((uint32_t)((nj*16 + (lane & 15))*128) + kb);
                LDSM4(vfh[2*nj][0], vfh[2*nj+1][0], vfh[2*nj][1], vfh[2*nj+1][1], sb + 32768 + sw);
                LDSM4(vfl[2*nj][0], vfl[2*nj+1][0], vfl[2*nj][1], vfl[2*nj+1][1], sb + 49152 + sw);
            }
            #pragma unroll
            for (int j8 = 0; j8 < 16; j8++) MMA_BF16(acc_o[j8], Ph[j], vfh[j8]);
            #pragma unroll
            for (int j8 = 0; j8 < 16; j8++) MMA_BF16(acc_o[j8], Ph[j], vfl[j8]);
            #pragma unroll
            for (int j8 = 0; j8 < 16; j8++) MMA_BF16(acc_o[j8], Pl[j], vfh[j8]);
        }

        __syncthreads();
        if (t + 2 < S_/64) LOAD_KV(t + 2);
    }

    const float inv1 = 1.f / l1, inv2 = 1.f / l2;
    const int r1 = q0 + w*16 + (lane >> 2);
    #pragma unroll
    for (int t8 = 0; t8 < 16; t8++) {
        const int c = h*HD_ + t8*8 + (lane & 3)*2;
        __nv_bfloat162 lo1, lo2;
        __nv_bfloat162 hi1 = split_pair(acc_o[t8][0]*inv1, acc_o[t8][1]*inv1, &lo1);
        __nv_bfloat162 hi2 = split_pair(acc_o[t8][2]*inv2, acc_o[t8][3]*inv2, &lo2);
        *(__nv_bfloat162*)(Oh + (size_t)(b*S_ + r1)*D_ + c)     = hi1;
        *(__nv_bfloat162*)(Ol + (size_t)(b*S_ + r1)*D_ + c)     = lo1;
        *(__nv_bfloat162*)(Oh + (size_t)(b*S_ + r1 + 8)*D_ + c) = hi2;
        *(__nv_bfloat162*)(Ol + (size_t)(b*S_ + r1 + 8)*D_ + c) = lo2;
    }
    #undef LOAD_KV
}

// ---------------------------------------------------------------------------
// Launch
// ---------------------------------------------------------------------------
extern "C" void kernel_launch(void* const* d_in, const int* in_sizes, int n_in,
                              void* d_out, int out_size)
{
    const float* x  = (const float*)d_in[0];
    const float* fc = (const float*)d_in[1];
    const float* fs = (const float*)d_in[2];
    const float* wq = (const float*)d_in[3];
    const float* wk = (const float*)d_in[4];
    const float* wv = (const float*)d_in[5];
    const float* wo = (const float*)d_in[6];
    float* out = (float*)d_out;

    __nv_bfloat16 *xh, *xl, *qh, *ql, *kh, *kl, *vth, *vtl, *oh, *ol;
    __nv_bfloat16 *wh, *wl, *woh, *wol;
    cudaGetSymbolAddress((void**)&xh,  g_xh);
    cudaGetSymbolAddress((void**)&xl,  g_xl);
    cudaGetSymbolAddress((void**)&qh,  g_qh);
    cudaGetSymbolAddress((void**)&ql,  g_ql);
    cudaGetSymbolAddress((void**)&kh,  g_kh);
    cudaGetSymbolAddress((void**)&kl,  g_kl);
    cudaGetSymbolAddress((void**)&vth, g_vth);
    cudaGetSymbolAddress((void**)&vtl, g_vtl);
    cudaGetSymbolAddress((void**)&oh,  g_oh);
    cudaGetSymbolAddress((void**)&ol,  g_ol);
    cudaGetSymbolAddress((void**)&wh,  g_wh);
    cudaGetSymbolAddress((void**)&wl,  g_wl);
    cudaGetSymbolAddress((void**)&woh, g_woh);
    cudaGetSymbolAddress((void**)&wol, g_wol);

    cudaFuncSetAttribute(gemm_qkv, cudaFuncAttributeMaxDynamicSharedMemorySize, GEMM_SMEM);
    cudaFuncSetAttribute(gemm_wo,  cudaFuncAttributeMaxDynamicSharedMemorySize, GEMM_SMEM);
    cudaFuncSetAttribute(attn_mma, cudaFuncAttributeMaxDynamicSharedMemorySize, AT_SMEM);

    // 1) conversions: x split; weights -> [N,K] rows concatenated [wq|wk|wv]
    split_fp32<<<(M_*D_/4 + 255)/256, 256>>>(x, xh, xl, M_*D_);
    transpose_split<<<dim3(D_/32,   D_/32), 256>>>(wq, wh,              wl,              D_, D_);
    transpose_split<<<dim3(KVD_/32, D_/32), 256>>>(wk, wh + (size_t)D_*D_, wl + (size_t)D_*D_, D_, KVD_);
    transpose_split<<<dim3(KVD_/32, D_/32), 256>>>(wv, wh + (size_t)(D_+KVD_)*D_, wl + (size_t)(D_+KVD_)*D_, D_, KVD_);
    transpose_split<<<dim3(D_/32,   D_/32), 256>>>(wo, woh, wol, D_, D_);

    // 2) fused QKV projection + rope/split/transpose epilogues
    gemm_qkv<<<dim3(NQKV/128, M_/128), 256, GEMM_SMEM>>>(xh, xl, wh, wl,
        qh, ql, kh, kl, vth, vtl, fc, fs);

    // 3) attention
    attn_mma<<<dim3(S_/128, H_, B_), 256, AT_SMEM>>>(qh, ql, kh, kl, vth, vtl, oh, ol);

    // 4) output projection
    gemm_wo<<<dim3(D_/128, M_/128), 256, GEMM_SMEM>>>(oh, ol, woh, wol, out);
}